// round 16
// baseline (speedup 1.0000x reference)
#include <cuda_runtime.h>
#include <cuda_fp16.h>

#define ALPHA 0.2f
#define B_TOT 65536
#define TILES 4

typedef unsigned int u32;

// ---- persistent prepped constants ----
__device__ float d_wa1[128];
// W pre-shuffled into m16n8k16 B-fragment order:
// index = ((qw*2 + np)*8 + ks)*32 + lane, each entry = the 4 u32 regs ldsm4 would yield.
__device__ uint4 d_Wfrag[2048];   // 32 KB

__global__ void prep_kernel(const float* __restrict__ W, const float* __restrict__ a) {
    int blk = blockIdx.x, tid = threadIdx.x;
    if (blk < 64) {
        if (tid < 32) {
            int qw = blk >> 4, np = (blk >> 3) & 1, ks = blk & 7;
            int l = tid;
            int n0 = qw * 32 + np * 16 + (l >> 2);
            int k0 = ks * 16 + (l & 3) * 2;
            __half2 p0 = __floats2half2_rn(W[k0 * 128 + n0],        W[(k0 + 1) * 128 + n0]);
            __half2 p1 = __floats2half2_rn(W[(k0 + 8) * 128 + n0],  W[(k0 + 9) * 128 + n0]);
            __half2 p2 = __floats2half2_rn(W[k0 * 128 + n0 + 8],    W[(k0 + 1) * 128 + n0 + 8]);
            __half2 p3 = __floats2half2_rn(W[(k0 + 8) * 128 + n0 + 8], W[(k0 + 9) * 128 + n0 + 8]);
            uint4 v;
            v.x = *(u32*)&p0; v.y = *(u32*)&p1; v.z = *(u32*)&p2; v.w = *(u32*)&p3;
            d_Wfrag[blk * 32 + l] = v;
        }
    } else if (tid < 32) {
        int f = blk - 64;
        float4 wv = *(const float4*)(W + f * 128 + tid * 4);
        float4 av = *(const float4*)(a + tid * 4);
        float p = wv.x * av.x + wv.y * av.y + wv.z * av.z + wv.w * av.w;
#pragma unroll
        for (int off = 16; off; off >>= 1) p += __shfl_xor_sync(0xFFFFFFFFu, p, off);
        if (tid == 0) d_wa1[f] = p;
    }
}

// ---- smem layout ----
#define ROWB 272
#define PANELB 8704
#define OFF_H   (2 * PANELB)            // 17408: 8 warps x 4096 (h tile buffer)
#define OFF_ADJ (OFF_H + 8 * 4096)      // 50176: 2 bufs x 8 warps x 256 (adj, ping-pong)
#define SMEM_BYTES (OFF_ADJ + 2 * 8 * 256)  // 54272; x3 CTAs = 162816

__device__ __forceinline__ u32 smem_u32(const void* p) {
    u32 a;
    asm("{ .reg .u64 t; cvta.to.shared.u64 t, %1; cvt.u32.u64 %0, t; }" : "=r"(a) : "l"(p));
    return a;
}
__device__ __forceinline__ void ldsm4(u32* r, u32 addr) {
    asm volatile("ldmatrix.sync.aligned.m8n8.x4.shared.b16 {%0,%1,%2,%3}, [%4];"
                 : "=r"(r[0]), "=r"(r[1]), "=r"(r[2]), "=r"(r[3]) : "r"(addr));
}
__device__ __forceinline__ void mma16816(float* c, const u32* a, u32 b0, u32 b1) {
    asm volatile("mma.sync.aligned.m16n8k16.row.col.f32.f16.f16.f32 "
                 "{%0,%1,%2,%3}, {%4,%5,%6,%7}, {%8,%9}, {%0,%1,%2,%3};"
                 : "+f"(c[0]), "+f"(c[1]), "+f"(c[2]), "+f"(c[3])
                 : "r"(a[0]), "r"(a[1]), "r"(a[2]), "r"(a[3]), "r"(b0), "r"(b1));
}
__device__ __forceinline__ void cp_async16(u32 dst, const void* src) {
    asm volatile("cp.async.ca.shared.global [%0], [%1], 16;" :: "r"(dst), "l"(src) : "memory");
}
__device__ __forceinline__ void cp_async8(u32 dst, const void* src) {
    asm volatile("cp.async.ca.shared.global [%0], [%1], 8;" :: "r"(dst), "l"(src) : "memory");
}

// attention + fold for ONE batch; hv in regs, adj from smem; writes 8 fp16 rows of quad A panel
__device__ __forceinline__ void attention_fold(
    const float4* hv, const char* adj_s,
    float4 an, float4 v1, int lane, char* Ah, int row_base)
{
    const float4* adj4 = (const float4*)adj_s;
    float4 A0 = adj4[0], A1 = adj4[1];

    // ---- 16 simultaneous 128-dim dots: halving-exchange multi-value reduction ----
    float vals[16];
#pragma unroll
    for (int j = 0; j < 8; j++) {
        vals[j]     = hv[j].x * an.x + hv[j].y * an.y + hv[j].z * an.z + hv[j].w * an.w;
        vals[8 + j] = hv[j].x * v1.x + hv[j].y * v1.y + hv[j].z * v1.z + hv[j].w * v1.w;
    }
#pragma unroll
    for (int i = 0; i < 8; i++) {      // stage m=16
        bool hi = (lane & 16) != 0;
        float snd = hi ? vals[i] : vals[i + 8];
        float kp  = hi ? vals[i + 8] : vals[i];
        vals[i] = kp + __shfl_xor_sync(0xFFFFFFFFu, snd, 16);
    }
#pragma unroll
    for (int i = 0; i < 4; i++) {      // stage m=8
        bool hi = (lane & 8) != 0;
        float snd = hi ? vals[i] : vals[i + 4];
        float kp  = hi ? vals[i + 4] : vals[i];
        vals[i] = kp + __shfl_xor_sync(0xFFFFFFFFu, snd, 8);
    }
#pragma unroll
    for (int i = 0; i < 2; i++) {      // stage m=4
        bool hi = (lane & 4) != 0;
        float snd = hi ? vals[i] : vals[i + 2];
        float kp  = hi ? vals[i + 2] : vals[i];
        vals[i] = kp + __shfl_xor_sync(0xFFFFFFFFu, snd, 4);
    }
    {                                   // stage m=2
        bool hi = (lane & 2) != 0;
        float snd = hi ? vals[0] : vals[1];
        float kp  = hi ? vals[1] : vals[0];
        vals[0] = kp + __shfl_xor_sync(0xFFFFFFFFu, snd, 2);
    }
    vals[0] += __shfl_xor_sync(0xFFFFFFFFu, vals[0], 1);   // final m=1
    float en[8], s1[8];
#pragma unroll
    for (int j = 0; j < 8; j++) {
        en[j] = __shfl_sync(0xFFFFFFFFu, vals[0], 2 * j);
        s1[j] = __shfl_sync(0xFFFFFFFFu, vals[0], 16 + 2 * j);
    }

    // ---- node softmax (leaky; logits |x|<~3, raw exp safe) + residual scale ----
    float sum = 0.f;
#pragma unroll
    for (int j = 0; j < 8; j++) {
        float v = en[j] > 0.f ? en[j] : ALPHA * en[j];
        float p = __expf(v);
        en[j] = p;
        sum += p;
    }
    float inv = 1.f / sum;
    float scale[8], u[8], w[8];
#pragma unroll
    for (int j = 0; j < 8; j++) {
        float sc = 1.f + en[j] * inv;
        scale[j] = sc;
        u[j] = __expf(sc * s1[j]);     // Wh2[i] cancels in the row softmax
        w[j] = u[j] * scale[j];
    }

#pragma unroll
    for (int i = 0; i < 8; i++) {
        float adv[8] = {A0.x, A0.y, A0.z, A0.w, A1.x, A1.y, A1.z, A1.w};
        if (i < 7) { A0 = adj4[2 * (i + 1)]; A1 = adj4[2 * (i + 1) + 1]; }

        float s = adv[0] * u[0];
        s = fmaf(adv[1], u[1], s); s = fmaf(adv[2], u[2], s); s = fmaf(adv[3], u[3], s);
        s = fmaf(adv[4], u[4], s); s = fmaf(adv[5], u[5], s); s = fmaf(adv[6], u[6], s);
        s = fmaf(adv[7], u[7], s);
        float c[8], is;
        if (s != 0.f) {                       // warp-uniform branch
            is = __fdividef(1.f, s);
#pragma unroll
            for (int j = 0; j < 8; j++) c[j] = adv[j] * w[j];
        } else {                              // fully-masked row: uniform 1/8
            is = 0.125f;
#pragma unroll
            for (int j = 0; j < 8; j++) c[j] = scale[j];
        }
        float4 g = make_float4(0.f, 0.f, 0.f, 0.f);
#pragma unroll
        for (int j = 0; j < 8; j++) {
            g.x = fmaf(c[j], hv[j].x, g.x);
            g.y = fmaf(c[j], hv[j].y, g.y);
            g.z = fmaf(c[j], hv[j].z, g.z);
            g.w = fmaf(c[j], hv[j].w, g.w);
        }
        g.x *= is; g.y *= is; g.z *= is; g.w *= is;

        __half2 h01 = __floats2half2_rn(g.x, g.y);
        __half2 h23 = __floats2half2_rn(g.z, g.w);
        uint2 uh = make_uint2(*(u32*)&h01, *(u32*)&h23);
        *(uint2*)(Ah + (row_base + i) * ROWB + lane * 8) = uh;
    }
}

__global__ __launch_bounds__(256, 3) void fused_gat_hmma(
    const float* __restrict__ h, const float* __restrict__ adj,
    const float* __restrict__ a_node, float* __restrict__ out)
{
    extern __shared__ char sm[];
    const u32 smb = smem_u32(sm);
    int tid = threadIdx.x, lane = tid & 31, warp = tid >> 5;
    int quad = warp >> 2, qw = warp & 3;     // 2 quads/CTA, 4 warps each

    const int cta_b0 = blockIdx.x * (8 * TILES);
    const int woff = quad * 4 + qw;          // warp's batch offset within a tile

    const u32 hbuf = smb + (u32)(OFF_H + warp * 4096);
    const u32 abuf[2] = { smb + (u32)(OFF_ADJ + warp * 256),
                          smb + (u32)(OFF_ADJ + 2048 + warp * 256) };

    // ---- prefetch tile 0 (h + adj) via cp.async ----
    {
        int b = cta_b0 + woff;
        const float* hb = h + (size_t)b * 1024;
#pragma unroll
        for (int j = 0; j < 8; j++)
            cp_async16(hbuf + j * 512 + lane * 16, hb + j * 128 + lane * 4);
        cp_async8(abuf[0] + lane * 8, adj + (size_t)b * 64 + lane * 2);
        asm volatile("cp.async.commit_group;" ::: "memory");
    }

    float4 an = *(const float4*)(a_node + lane * 4);
    float4 v1 = *(const float4*)(d_wa1 + lane * 4);

    char* Ah = sm + quad * PANELB;
    const int rb = qw * 8;
    const u32 ah_base = smb + (u32)(quad * PANELB);
    const u32 a_off = (u32)((lane & 15) * ROWB + (lane >> 4) * 16);
    const uint4* __restrict__ Wf = d_Wfrag + (size_t)qw * 512 + lane;

#pragma unroll 1
    for (int t = 0; t < TILES; t++) {
        const int bq = cta_b0 + t * 8 + quad * 4;

        // wait for this tile's prefetch; make it warp-visible
        asm volatile("cp.async.wait_group 0;" ::: "memory");
        __syncwarp();

        // hv from smem (29cyc LDS instead of exposed DRAM)
        float4 hv[8];
#pragma unroll
        for (int j = 0; j < 8; j++)
            hv[j] = *(const float4*)(sm + (hbuf - smb) + j * 512 + lane * 16);

        // issue next tile's prefetch (lands under fold + GEMM)
        if (t + 1 < TILES) {
            int bn = cta_b0 + (t + 1) * 8 + woff;
            const float* hb = h + (size_t)bn * 1024;
#pragma unroll
            for (int j = 0; j < 8; j++)
                cp_async16(hbuf + j * 512 + lane * 16, hb + j * 128 + lane * 4);
            cp_async8(abuf[(t + 1) & 1] + lane * 8, adj + (size_t)bn * 64 + lane * 2);
            asm volatile("cp.async.commit_group;" ::: "memory");
        }

        attention_fold(hv, sm + (abuf[t & 1] - smb), an, v1, lane, Ah, rb);

        // quad barrier: all 4 warps' A rows visible before cross-read
        asm volatile("bar.sync %0, 128;" :: "r"(quad + 1) : "memory");

        // ====== HMMA GEMM: rows 0..31 x this warp's 32-col quarter ======
        float acc[8][4];
#pragma unroll
        for (int q = 0; q < 8; q++) { acc[q][0] = acc[q][1] = acc[q][2] = acc[q][3] = 0.f; }

#pragma unroll
        for (int ks = 0; ks < 8; ks++) {
            u32 afh[2][4];
#pragma unroll
            for (int mt = 0; mt < 2; mt++)
                ldsm4(afh[mt], ah_base + a_off + mt * (16 * ROWB) + ks * 32);
#pragma unroll
            for (int np = 0; np < 2; np++) {
                uint4 bh = __ldg(Wf + (np * 8 + ks) * 32);
#pragma unroll
                for (int mt = 0; mt < 2; mt++) {
                    mma16816(acc[mt * 4 + 2 * np],     afh[mt], bh.x, bh.y);
                    mma16816(acc[mt * 4 + 2 * np + 1], afh[mt], bh.z, bh.w);
                }
            }
        }

        // panel reads done -> partners may start next fold while I do the epilogue
        if (t + 1 < TILES)
            asm volatile("bar.sync %0, 128;" :: "r"(quad + 1) : "memory");

        // ---- epilogue: relu + store ----
#pragma unroll
        for (int mt = 0; mt < 2; mt++) {
            float* o0 = out + ((size_t)(bq + mt * 2) * 8 + (lane >> 2)) * 128 +
                        qw * 32 + (lane & 3) * 2;
            float* o1 = o0 + 1024;
#pragma unroll
            for (int nt = 0; nt < 4; nt++) {
                float* ac = acc[mt * 4 + nt];
                float2 r0 = make_float2(fmaxf(ac[0], 0.f), fmaxf(ac[1], 0.f));
                float2 r1 = make_float2(fmaxf(ac[2], 0.f), fmaxf(ac[3], 0.f));
                *(float2*)(o0 + nt * 8) = r0;
                *(float2*)(o1 + nt * 8) = r1;
            }
        }
    }
}

extern "C" void kernel_launch(void* const* d_in, const int* in_sizes, int n_in,
                              void* d_out, int out_size) {
    const float* h      = (const float*)d_in[0];
    const float* adj    = (const float*)d_in[1];
    const float* W      = (const float*)d_in[2];
    const float* a      = (const float*)d_in[3];
    const float* a_node = (const float*)d_in[4];
    float* out = (float*)d_out;

    prep_kernel<<<192, 256>>>(W, a);

    cudaFuncSetAttribute(fused_gat_hmma, cudaFuncAttributeMaxDynamicSharedMemorySize, SMEM_BYTES);
    fused_gat_hmma<<<B_TOT / (8 * TILES), 256, SMEM_BYTES>>>(h, adj, a_node, out);
}